// round 2
// baseline (speedup 1.0000x reference)
#include <cuda_runtime.h>
#include <cstdint>

// SpatialCoherenceConv reduced form:
//   result = (1/B) * sum_{b,c,h,w} [ (81 + cw(h)*cw(w)) * x^2 - 2 * x * box9(x) ]
// box9 = zero-padded 9x9 box sum (separable); cw(i) = #windows covering i.
//
// Single fused kernel: vertical running sum in registers (10-deep float4
// pipeline, compile-time indices via 20-row unroll period), horizontal 9-sum
// via shared halo exchange (2 rows per __syncthreads, 2 buffer pairs),
// grid-wide sum folded in via last-block-done pattern (deterministic).

#define HH 512
#define WW 512
#define KRAD 4
#define CPT 4
#define TPB 128
#define STRIP 64
#define TILES (HH / STRIP)   // 8
#define NBLK_MAX 4096

__device__ double g_partials[NBLK_MAX];
__device__ unsigned int g_count = 0;

__device__ __forceinline__ float cw_of(int i, int n) {
    int l = (i < KRAD) ? (KRAD - i) : 0;
    int r = (i > n - 1 - KRAD) ? (i - (n - 1 - KRAD)) : 0;
    return (float)(2 * KRAD + 1 - l - r);
}

__device__ __forceinline__ void accum_row(int r, float4 vs, float4 L, float4 R,
                                          float4 xc, float4 wc, float4& acc) {
    float vall = (vs.x + vs.y) + (vs.z + vs.w);
    float h0 = ((L.x + L.y) + (L.z + L.w)) + vall + R.x;
    float h1 = h0 - L.x + R.y;
    float h2 = h1 - L.y + R.z;
    float h3 = h2 - L.z + R.w;
    float wr = cw_of(r, HH);
    float cf0 = fmaf(wr, wc.x, 81.f);
    float cf1 = fmaf(wr, wc.y, 81.f);
    float cf2 = fmaf(wr, wc.z, 81.f);
    float cf3 = fmaf(wr, wc.w, 81.f);
    float v0 = fmaf(cf0, xc.x, -(h0 + h0));
    float v1 = fmaf(cf1, xc.y, -(h1 + h1));
    float v2 = fmaf(cf2, xc.z, -(h2 + h2));
    float v3 = fmaf(cf3, xc.w, -(h3 + h3));
    acc.x = fmaf(xc.x, v0, acc.x);
    acc.y = fmaf(xc.y, v1, acc.y);
    acc.z = fmaf(xc.z, v2, acc.z);
    acc.w = fmaf(xc.w, v3, acc.w);
}

// Processes rows (rbase+PH, rbase+PH+1). PH is a literal (even, 0..18);
// PR in {0,1} alternates per body. Pipe slot for row rr = (rr - r0 + 4) % 10.
#define BODY2(PH, PR) do {                                                     \
    const int ra = rbase + (PH);                                               \
    *(float4*)&vsbuf[2*(PR)][KRAD + c0] = vsum;                                \
    const float4 vs_a = vsum;                                                  \
    {   int rr = ra + 5;                                                       \
        float4 nv = make_float4(0.f, 0.f, 0.f, 0.f);                           \
        if (rr < HH) nv = *(const float4*)(P + (size_t)rr * WW + c0);          \
        const float4 ov = pipe[(PH) % 10];                                     \
        vsum.x += nv.x - ov.x; vsum.y += nv.y - ov.y;                          \
        vsum.z += nv.z - ov.z; vsum.w += nv.w - ov.w;                          \
        pipe[((PH) + 9) % 10] = nv; }                                          \
    *(float4*)&vsbuf[2*(PR)+1][KRAD + c0] = vsum;                              \
    const float4 vs_b = vsum;                                                  \
    {   int rr = ra + 6;                                                       \
        float4 nv = make_float4(0.f, 0.f, 0.f, 0.f);                           \
        if (rr < HH) nv = *(const float4*)(P + (size_t)rr * WW + c0);          \
        const float4 ov = pipe[((PH) + 1) % 10];                               \
        vsum.x += nv.x - ov.x; vsum.y += nv.y - ov.y;                          \
        vsum.z += nv.z - ov.z; vsum.w += nv.w - ov.w;                          \
        pipe[((PH) + 10) % 10] = nv; }                                         \
    __syncthreads();                                                           \
    {   float4 L = *(const float4*)&vsbuf[2*(PR)][c0];                         \
        float4 R = *(const float4*)&vsbuf[2*(PR)][KRAD + c0 + 4];              \
        accum_row(ra, vs_a, L, R, pipe[((PH) + 4) % 10], wc, acc); }           \
    {   float4 L = *(const float4*)&vsbuf[2*(PR)+1][c0];                       \
        float4 R = *(const float4*)&vsbuf[2*(PR)+1][KRAD + c0 + 4];            \
        accum_row(ra + 1, vs_b, L, R, pipe[((PH) + 5) % 10], wc, acc); }       \
} while (0)

__global__ __launch_bounds__(TPB) void scc_main_kernel(const float* __restrict__ img,
                                                       float* __restrict__ out,
                                                       double inv_b) {
    const int bid   = blockIdx.x;
    const int plane = bid / TILES;
    const int tile  = bid % TILES;
    const int r0    = tile * STRIP;
    const float* __restrict__ P = img + (size_t)plane * (HH * WW);

    const int tid = threadIdx.x;
    const int c0  = tid * CPT;

    __shared__ float vsbuf[4][WW + 2 * KRAD];  // 2 buffer pairs + zero halos
    __shared__ double sred[4];
    __shared__ int slast;

    // zero the horizontal halos once (4 buffers x 8 halo cells)
    if (tid < 32) {
        int b = tid >> 3;
        int i = tid & 7;
        int idx = (i < KRAD) ? i : (WW + i);   // 0..3 and 516..519
        vsbuf[b][idx] = 0.0f;
    }

    float4 wc = make_float4(cw_of(c0 + 0, WW), cw_of(c0 + 1, WW),
                            cw_of(c0 + 2, WW), cw_of(c0 + 3, WW));

    // prefill pipeline: rows r0-4 .. r0+4 -> slots 0..8; build vertical sum
    float4 pipe[10];
    float4 vsum = make_float4(0.f, 0.f, 0.f, 0.f);
    #pragma unroll
    for (int i = 0; i < 9; i++) {
        int rr = r0 - KRAD + i;
        float4 v = make_float4(0.f, 0.f, 0.f, 0.f);
        if (rr >= 0) v = *(const float4*)(P + (size_t)rr * WW + c0);
        pipe[i] = v;
        vsum.x += v.x; vsum.y += v.y; vsum.z += v.z; vsum.w += v.w;
    }
    pipe[9] = make_float4(0.f, 0.f, 0.f, 0.f);

    float4 acc = make_float4(0.f, 0.f, 0.f, 0.f);

    // 64 rows = 3 x 20 + 4; pipe period 10, pair period 4 rows -> unroll 20
    for (int ro = 0; ro < STRIP - 4; ro += 20) {
        const int rbase = r0 + ro;
        BODY2(0, 0);  BODY2(2, 1);  BODY2(4, 0);  BODY2(6, 1);  BODY2(8, 0);
        BODY2(10, 1); BODY2(12, 0); BODY2(14, 1); BODY2(16, 0); BODY2(18, 1);
    }
    {
        const int rbase = r0 + (STRIP - 4);
        BODY2(0, 0);  BODY2(2, 1);
    }

    // block reduction (double, fixed order)
    double d = ((double)acc.x + (double)acc.y) + ((double)acc.z + (double)acc.w);
    #pragma unroll
    for (int off = 16; off > 0; off >>= 1)
        d += __shfl_down_sync(0xffffffffu, d, off);

    const int warp = tid >> 5;
    const int lane = tid & 31;
    if (lane == 0) sred[warp] = d;
    __syncthreads();
    if (tid == 0) {
        g_partials[bid] = (sred[0] + sred[1]) + (sred[2] + sred[3]);
        __threadfence();
        unsigned int old = atomicAdd(&g_count, 1u);
        slast = (old == gridDim.x - 1) ? 1 : 0;
    }
    __syncthreads();

    // last block performs the grid reduction (order-fixed -> deterministic)
    if (slast) {
        __threadfence();
        double t = 0.0;
        const int nb = gridDim.x;
        for (int i = tid; i < nb; i += TPB)
            t += g_partials[i];
        #pragma unroll
        for (int off = 16; off > 0; off >>= 1)
            t += __shfl_down_sync(0xffffffffu, t, off);
        if (lane == 0) sred[warp] = t;
        __syncthreads();
        if (tid == 0) {
            double tot = (sred[0] + sred[1]) + (sred[2] + sred[3]);
            out[0] = (float)(tot * inv_b);
            g_count = 0;   // reset for next graph replay
        }
    }
}

extern "C" void kernel_launch(void* const* d_in, const int* in_sizes, int n_in,
                              void* d_out, int out_size) {
    const float* img = (const float*)d_in[0];
    float* out = (float*)d_out;

    int nplanes = in_sizes[0] / (HH * WW);   // B*C = 256
    int batch   = nplanes / 32;              // C = 32 -> B = 8
    int nblocks = nplanes * TILES;           // 2048

    scc_main_kernel<<<nblocks, TPB>>>(img, out, 1.0 / (double)batch);
}